// round 6
// baseline (speedup 1.0000x reference)
#include <cuda_runtime.h>

// HN=10, ND=40, HF=8 (fixed). A_ENC: agg[j]=sum x[4j-3..4j+2 mod 40].
// A_PRED: agg2[d]=z1[d]+w*(z1[d-1]+z1[d+1]), w=exp(-1/9).
// A_DEC per grid i (m=i%4): m0:s[c]; m1,m2:s[c]+s[c+1]; m3:s[c+1]  (c=i/4, wrap mod 10)

typedef unsigned long long u64;

__device__ __forceinline__ u64 pk2(float a, float b) {
    u64 r; asm("mov.b64 %0, {%1, %2};" : "=l"(r) : "f"(a), "f"(b)); return r;
}
__device__ __forceinline__ void upk2(u64 v, float& a, float& b) {
    asm("mov.b64 {%0, %1}, %2;" : "=f"(a), "=f"(b) : "l"(v));
}
__device__ __forceinline__ u64 ffma2(u64 a, u64 b, u64 c) {
    u64 d; asm("fma.rn.f32x2 %0, %1, %2, %3;" : "=l"(d) : "l"(a), "l"(b), "l"(c)); return d;
}
__device__ __forceinline__ u64 add2(u64 a, u64 b) {
    u64 d; asm("add.rn.f32x2 %0, %1, %2;" : "=l"(d) : "l"(a), "l"(b)); return d;
}

// Shared weight table layout (u64 slots)
#define IW_ENCRW 0
#define IW_ENCB  4
#define IW_PREDB 8
#define IW_ENCW  12   // + g*4 + f2
#define IW_W1    44   // + g*4 + f2
#define IW_W2    76   // + g*4 + f2
#define IW_DRW   108  // 8 floats at u64 108..111
#define IW_DEC2  112  // 2 floats
#define SW_U64   128

#define ZROW 21       // float4 per element row (20 used; row = 84 floats = 42 u64)
#define SMEM_BYTES (SW_U64 * 8 + 128 * ZROW * 16)   // 1024 + 43008 = 44032

__global__ __launch_bounds__(128, 5)
void gnn_kernel(const float* __restrict__ x, const float* __restrict__ z,
                const float* __restrict__ y, float* __restrict__ out,
                const float* __restrict__ erw, const float* __restrict__ erb,
                const float* __restrict__ erow,
                const float* __restrict__ prw, const float* __restrict__ prb,
                const float* __restrict__ prow,
                const float* __restrict__ drw, const float* __restrict__ drb,
                const float* __restrict__ droot) {
    extern __shared__ u64 sw[];                 // [0,128) u64: packed weights
    float4* buf = (float4*)(sw + SW_U64);       // 128 rows * 21 float4

    const int t = threadIdx.x;
    const int blk = blockIdx.x;

    // ---- Per-block weight prep (L2-hit LDGs), concurrent with x staging ----
    if (t < 32) {
        const int g = t & 7, f2 = t >> 3;
        const int i0 = (2 * f2) * 8 + g;
        const int i1 = (2 * f2 + 1) * 8 + g;
        const float wE = 0.894839316814370f;    // exp(-1/9)
        sw[IW_ENCW + g * 4 + f2] = pk2(erow[i0], erow[i1]);
        sw[IW_W1   + g * 4 + f2] = pk2(prw[i0] + prow[i0], prw[i1] + prow[i1]);
        sw[IW_W2   + g * 4 + f2] = pk2(wE * prw[i0], wE * prw[i1]);
    } else if (t < 36) {
        const int q = t - 32;
        sw[IW_ENCRW + q] = pk2(erw[2 * q], erw[2 * q + 1]);
        sw[IW_ENCB  + q] = pk2(erb[2 * q], erb[2 * q + 1]);
        sw[IW_PREDB + q] = pk2(prb[2 * q], prb[2 * q + 1]);
    } else if (t < 44) {
        ((float*)(sw + IW_DRW))[t - 36] = drw[t - 36];
    } else if (t == 44) {
        ((float*)(sw + IW_DEC2))[0] = drb[0];
        ((float*)(sw + IW_DEC2))[1] = droot[0];
    }

    // ---- Phase 1: stage x coalesced into [128][11] float4 ----
    const float4* xg = (const float4*)x + (long long)blk * 1280;
#pragma unroll
    for (int k = 0; k < 10; k++) {
        const int i4 = t + k * 128;
        buf[(i4 / 10) * 11 + (i4 % 10)] = xg[i4];
    }
    __syncthreads();

    // ---- Phase 2: encoder ring aggregation ----
    float t1[10], t2[10];
#pragma unroll
    for (int c = 0; c < 10; c++) {
        const float4 v = buf[t * 11 + c];
        t1[c] = v.y + v.z + v.w;
        t2[c] = v.x + v.y + v.z;
    }
    float agg[10];
#pragma unroll
    for (int j = 0; j < 10; j++) agg[j] = t1[(j + 9) % 10] + t2[j];
    __syncthreads();   // x reads done before z overwrites buf

    // ---- Phase 3: stage z coalesced into [128][21] float4 ----
    const float4* zg = (const float4*)z + (long long)blk * 2560;
#pragma unroll
    for (int k = 0; k < 20; k++) {
        const int i4 = t + k * 128;
        buf[(i4 / 20) * ZROW + (i4 % 20)] = zg[i4];
    }
    __syncthreads();

    float4* row4 = buf + t * ZROW;      // own row: z node j at f4 slots 2j,2j+1
    u64*   myz1 = (u64*)row4;           // same row as u64 slots; z1[j][f2] -> 4j+f2

    // ======== Stage A (node halves): z1[j] = relu(agg[j]*erw + erb + z[j]@erow^T) ====
    // In-place: node j's z occupies u64 4j..4j+3 == z1 slots 4j..4j+3; reads of the
    // half's nodes all precede the half's writes, own row only -> no syncs needed.
#pragma unroll
    for (int jh = 0; jh < 2; jh++) {
        const int j0 = jh * 5;
        u64 zz[20];
        {
            const u64 rw0 = sw[IW_ENCRW], rw1 = sw[IW_ENCRW + 1];
            const u64 rw2 = sw[IW_ENCRW + 2], rw3 = sw[IW_ENCRW + 3];
            const u64 b0 = sw[IW_ENCB], b1 = sw[IW_ENCB + 1];
            const u64 b2 = sw[IW_ENCB + 2], b3 = sw[IW_ENCB + 3];
#pragma unroll
            for (int j5 = 0; j5 < 5; j5++) {
                const u64 ab = pk2(agg[j0 + j5], agg[j0 + j5]);
                zz[j5 * 4 + 0] = ffma2(ab, rw0, b0);
                zz[j5 * 4 + 1] = ffma2(ab, rw1, b1);
                zz[j5 * 4 + 2] = ffma2(ab, rw2, b2);
                zz[j5 * 4 + 3] = ffma2(ab, rw3, b3);
            }
        }
#pragma unroll 1
        for (int gh = 0; gh < 2; gh++) {
            u64 w[16];
#pragma unroll
            for (int gw = 0; gw < 4; gw++)
#pragma unroll
                for (int f2 = 0; f2 < 4; f2++)
                    w[gw * 4 + f2] = sw[IW_ENCW + (4 * gh + gw) * 4 + f2];
#pragma unroll
            for (int j5 = 0; j5 < 5; j5++) {
                const float4 zv = row4[2 * (j0 + j5) + gh];
                const float zsc[4] = {zv.x, zv.y, zv.z, zv.w};
#pragma unroll
                for (int gw = 0; gw < 4; gw++) {
                    const u64 zb = pk2(zsc[gw], zsc[gw]);
#pragma unroll
                    for (int f2 = 0; f2 < 4; f2++)
                        zz[j5 * 4 + f2] = ffma2(zb, w[gw * 4 + f2], zz[j5 * 4 + f2]);
                }
            }
        }
        // relu + pack + in-place store (own row)
#pragma unroll
        for (int j5 = 0; j5 < 5; j5++)
#pragma unroll
            for (int f2 = 0; f2 < 4; f2++) {
                float a, b; upk2(zz[j5 * 4 + f2], a, b);
                myz1[4 * (j0 + j5) + f2] = pk2(fmaxf(a, 0.0f), fmaxf(b, 0.0f));
            }
    }

    // ======== Stage B: z2[d] = relu(z1[d]@W1^T + (z1[d-1]+z1[d+1])@W2^T + prb) =====
    //          s[d] = z2[d]·drw, buffered in registers
    float sreg[10];
#pragma unroll
    for (int dh = 0; dh < 2; dh++) {
        u64 acc[20];
#pragma unroll
        for (int d5 = 0; d5 < 5; d5++)
#pragma unroll
            for (int f2 = 0; f2 < 4; f2++) acc[4 * d5 + f2] = sw[IW_PREDB + f2];

#pragma unroll 1
        for (int p = 0; p < 4; p++) {          // g-pair (2p, 2p+1)
            u64 w1lo[4], w1hi[4], w2lo[4], w2hi[4];
#pragma unroll
            for (int f2 = 0; f2 < 4; f2++) {
                w1lo[f2] = sw[IW_W1 + (2 * p) * 4 + f2];
                w1hi[f2] = sw[IW_W1 + (2 * p + 1) * 4 + f2];
                w2lo[f2] = sw[IW_W2 + (2 * p) * 4 + f2];
                w2hi[f2] = sw[IW_W2 + (2 * p + 1) * 4 + f2];
            }
            u64 zr[7];
#pragma unroll
            for (int k = 0; k < 7; k++)
                zr[k] = myz1[4 * ((dh * 5 + k + 9) % 10) + p];
#pragma unroll
            for (int d5 = 0; d5 < 5; d5++) {
                const u64 zd = zr[d5 + 1];
                const u64 up = add2(zr[d5], zr[d5 + 2]);
                float zl, zh, ul, uh;
                upk2(zd, zl, zh); upk2(up, ul, uh);
                const u64 bzl = pk2(zl, zl), bzh = pk2(zh, zh);
                const u64 bul = pk2(ul, ul), buh = pk2(uh, uh);
#pragma unroll
                for (int f2 = 0; f2 < 4; f2++) {
                    u64 a = acc[4 * d5 + f2];
                    a = ffma2(bzl, w1lo[f2], a);
                    a = ffma2(bzh, w1hi[f2], a);
                    a = ffma2(bul, w2lo[f2], a);
                    a = ffma2(buh, w2hi[f2], a);
                    acc[4 * d5 + f2] = a;
                }
            }
        }
        {
            const float* dw = (const float*)(sw + IW_DRW);
#pragma unroll
            for (int d5 = 0; d5 < 5; d5++) {
                float f0, f1, f2v, f3, f4v, f5, f6, f7;
                upk2(acc[4 * d5 + 0], f0, f1);
                upk2(acc[4 * d5 + 1], f2v, f3);
                upk2(acc[4 * d5 + 2], f4v, f5);
                upk2(acc[4 * d5 + 3], f6, f7);
                sreg[dh * 5 + d5] =
                      fmaxf(f0, 0.0f) * dw[0] + fmaxf(f1, 0.0f) * dw[1]
                    + fmaxf(f2v, 0.0f) * dw[2] + fmaxf(f3, 0.0f) * dw[3]
                    + fmaxf(f4v, 0.0f) * dw[4] + fmaxf(f5, 0.0f) * dw[5]
                    + fmaxf(f6, 0.0f) * dw[6] + fmaxf(f7, 0.0f) * dw[7];
            }
        }
    }
    // write s into own row tail (floats 74..83; all own-row z1 reads are complete)
    {
        float* srow = (float*)row4;
#pragma unroll
        for (int d = 0; d < 10; d++) srow[74 + d] = sreg[d];
    }
    __syncthreads();

    // ---- Decoder/output: fully coalesced float4 y-load + out-store ----
    const float drbv   = ((const float*)(sw + IW_DEC2))[0];
    const float drootv = ((const float*)(sw + IW_DEC2))[1];
    const float* sf = (const float*)buf;     // s[e][d] at float 84*e + 74 + d
    const float4* yg = (const float4*)y + (long long)blk * 1280;
    float4* og = (float4*)out + (long long)blk * 1280;
#pragma unroll
    for (int p = 0; p < 10; p++) {
        const int n4 = t + p * 128;
        const int bl = n4 / 10, c = n4 % 10;
        const float sa = sf[84 * bl + 74 + c];
        const float sb = sf[84 * bl + 74 + ((c == 9) ? 0 : c + 1)];
        const float4 yv = yg[n4];
        float4 o;
        o.x = sa + drbv + yv.x * drootv;          // m=0
        o.y = sa + sb + drbv + yv.y * drootv;     // m=1
        o.z = sa + sb + drbv + yv.z * drootv;     // m=2
        o.w = sb + drbv + yv.w * drootv;          // m=3
        og[n4] = o;
    }
}

extern "C" void kernel_launch(void* const* d_in, const int* in_sizes, int n_in,
                              void* d_out, int out_size) {
    const float* x     = (const float*)d_in[0];
    const float* z     = (const float*)d_in[1];
    const float* y     = (const float*)d_in[2];
    const float* erw   = (const float*)d_in[3];
    const float* erb   = (const float*)d_in[4];
    const float* erow  = (const float*)d_in[5];
    const float* prw   = (const float*)d_in[6];
    const float* prb   = (const float*)d_in[7];
    const float* prow  = (const float*)d_in[8];
    const float* drw   = (const float*)d_in[9];
    const float* drb   = (const float*)d_in[10];
    const float* droot = (const float*)d_in[11];

    const int B = in_sizes[0] / 40;       // 524288
    const int blocks = B / 128;           // 4096

    gnn_kernel<<<blocks, 128, SMEM_BYTES>>>(x, z, y, (float*)d_out,
                                            erw, erb, erow, prw, prb, prow,
                                            drw, drb, droot);
}